// round 4
// baseline (speedup 1.0000x reference)
#include <cuda_runtime.h>
#include <cstdint>

// ----------------------------------------------------------------------------
// TitleGenerator: 400-step GRU rollout, B=2048, D=4096, H=128, C=96.
// Strategy:
//  - prep kernel: repack weights (lin1 transpose; combined GRU+lin2 matrix,
//    exploiting x==h after step 1: rows [0,256)=w_ih+w_hh (r,z), [256,384)=w_ih_n,
//    [384,512)=w_hh_n, [512,608)=lin2_w). Step-1 variant has h-rows zeroed.
//  - k0 kernel: ht = leaky(img_feat @ lin1_w.T + b1)
//  - main persistent kernel: 148 CTAs x 608 threads, 13-14 batch rows each,
//    all 400 steps in one launch. fp32 f32x2 packed FMA (row pairs).
//    Bitwise fixed-point detection -> pure-store fast path.
// ----------------------------------------------------------------------------

#define BB      2048
#define DD      4096
#define HH      128
#define CC      96
#define TSTEPS  400
#define MM      608
#define NT      608
#define PAIRS   7
#define TITLES_ELEMS 78643200   // 2048*400*96

static __device__ float4 g_W1t4[1024 * 128];   // lin1 transposed, float4 over k
static __device__ float4 g_Wc4 [32 * 608];     // combined weights, [j4][i] float4 over j
static __device__ float4 g_W1c4[32 * 608];     // step-1 variant
static __device__ float  g_bc  [608];          // combined bias
static __device__ float  g_ht  [BB * HH];      // leaky(lin1(img))

__device__ __forceinline__ unsigned long long pk2(float lo, float hi) {
    unsigned long long r;
    asm("mov.b64 %0, {%1, %2};" : "=l"(r) : "f"(lo), "f"(hi));
    return r;
}
__device__ __forceinline__ void upk2(unsigned long long v, float& lo, float& hi) {
    asm("mov.b64 {%0, %1}, %2;" : "=f"(lo), "=f"(hi) : "l"(v));
}
#define FMA2(acc, a, b) asm("fma.rn.f32x2 %0, %1, %2, %3;" : "=l"(acc) : "l"(a), "l"(b), "l"(acc))

// ------------------------------- prep ---------------------------------------
__global__ void prep_kernel(const float* __restrict__ lin1_w,
                            const float* __restrict__ w_ih,
                            const float* __restrict__ w_hh,
                            const float* __restrict__ b_ih,
                            const float* __restrict__ b_hh,
                            const float* __restrict__ lin2_w,
                            const float* __restrict__ lin2_b) {
    int idx0 = blockIdx.x * blockDim.x + threadIdx.x;
    int stride = gridDim.x * blockDim.x;

    float* w1t = reinterpret_cast<float*>(g_W1t4);
    for (int idx = idx0; idx < 1024 * 128 * 4; idx += stride) {
        int k4 = idx >> 9;            // 512 floats per k4 block
        int j  = (idx >> 2) & 127;
        int c  = idx & 3;
        w1t[idx] = lin1_w[j * DD + (k4 * 4 + c)];
    }

    float* wc  = reinterpret_cast<float*>(g_Wc4);
    float* w1c = reinterpret_cast<float*>(g_W1c4);
    for (int idx = idx0; idx < 32 * 608 * 4; idx += stride) {
        int j4  = idx / 2432;
        int rem = idx - j4 * 2432;
        int i   = rem >> 2;
        int c   = rem & 3;
        int j   = j4 * 4 + c;
        float v, v1;
        if (i < 256)      { v = w_ih[i * HH + j] + w_hh[i * HH + j]; v1 = w_ih[i * HH + j]; }
        else if (i < 384) { v = w_ih[i * HH + j];                    v1 = v; }
        else if (i < 512) { v = w_hh[(i - 128) * HH + j];            v1 = 0.f; }
        else              { v = lin2_w[(i - 512) * HH + j];          v1 = 0.f; }
        wc[idx]  = v;
        w1c[idx] = v1;
    }

    for (int i = idx0; i < 608; i += stride) {
        float v;
        if (i < 256)      v = b_ih[i] + b_hh[i];
        else if (i < 384) v = b_ih[i];
        else if (i < 512) v = b_hh[i - 128];
        else              v = lin2_b[i - 512];
        g_bc[i] = v;
    }
}

// ------------------------------- k0: lin1 -----------------------------------
__global__ __launch_bounds__(256) void k0_kernel(const float* __restrict__ img,
                                                 const float* __restrict__ b1) {
    __shared__ __align__(16) float xs[8 * 128 * 2];  // 8 row-pairs x 128 k (float2)
    int tid = threadIdx.x;
    int j = tid & 127;
    int h = tid >> 7;              // 0/1: pair half
    int base = blockIdx.x * 16;

    unsigned long long acc[4];
#pragma unroll
    for (int p = 0; p < 4; p++) acc[p] = pk2(0.f, 0.f);

    for (int t = 0; t < 32; t++) {
        __syncthreads();
        for (int m = tid; m < 16 * 128; m += 256) {
            int r = m >> 7, kk = m & 127;
            xs[((r >> 1) * 128 + kk) * 2 + (r & 1)] =
                img[(size_t)(base + r) * DD + t * 128 + kk];
        }
        __syncthreads();
        const ulonglong2* xb = reinterpret_cast<const ulonglong2*>(xs);
#pragma unroll 4
        for (int k4 = 0; k4 < 32; k4++) {
            float4 w = g_W1t4[(t * 32 + k4) * 128 + j];
            unsigned long long w0 = pk2(w.x, w.x), w1 = pk2(w.y, w.y);
            unsigned long long w2 = pk2(w.z, w.z), w3 = pk2(w.w, w.w);
#pragma unroll
            for (int pp = 0; pp < 4; pp++) {
                int p = h * 4 + pp;
                ulonglong2 xa = xb[p * 64 + k4 * 2];
                ulonglong2 xc = xb[p * 64 + k4 * 2 + 1];
                FMA2(acc[pp], w0, xa.x);
                FMA2(acc[pp], w1, xa.y);
                FMA2(acc[pp], w2, xc.x);
                FMA2(acc[pp], w3, xc.y);
            }
        }
    }
    float bj = b1[j];
#pragma unroll
    for (int pp = 0; pp < 4; pp++) {
        float lo, hi;
        upk2(acc[pp], lo, hi);
        int r0 = h * 8 + 2 * pp;
        float v0 = lo + bj, v1 = hi + bj;
        g_ht[(base + r0) * HH + j]     = (v0 >= 0.f) ? v0 : 0.01f * v0;
        g_ht[(base + r0 + 1) * HH + j] = (v1 >= 0.f) ? v1 : 0.01f * v1;
    }
}

// ------------------------------- main ---------------------------------------
__global__ __launch_bounds__(608, 1) void main_kernel(float* __restrict__ out, int hasLens) {
    __shared__ __align__(16) float xpg[PAIRS * HH * 2];  // hidden, row-pair packed
    __shared__ __align__(16) float xpl[PAIRS * HH * 2];  // leaky(hidden)
    __shared__ float gsm[14 * 608];                      // matvec outputs, [row][i]
    __shared__ float msm[16];
    __shared__ int   lensm[16];

    const int tid = threadIdx.x;
    const int bid = blockIdx.x;
    int base, nv;
    if (bid < 124) { base = bid * 14; nv = 14; }
    else           { base = 1736 + (bid - 124) * 13; nv = 13; }

    for (int m = tid; m < PAIRS * HH * 2; m += NT) { xpg[m] = 0.f; xpl[m] = 0.f; }
    if (tid < 16) lensm[tid] = 0;
    __syncthreads();
    for (int m = tid; m < nv * HH; m += NT) {
        int r = m >> 7, k = m & 127;
        xpg[((r >> 1) * HH + k) * 2 + (r & 1)] = g_ht[(base + r) * HH + k];
    }
    __syncthreads();

    const float bias = g_bc[tid];
    const unsigned long long biasp = pk2(bias, bias);
    const ulonglong2* xb = (tid < 512) ? reinterpret_cast<const ulonglong2*>(xpg)
                                       : reinterpret_cast<const ulonglong2*>(xpl);

    // --- matvec phase: combined [608x128] against row-pair-packed x ----------
    auto matvec = [&](const float4* __restrict__ W4) {
        unsigned long long acc[PAIRS];
#pragma unroll
        for (int p = 0; p < PAIRS; p++) acc[p] = biasp;
        const float4* Wp = W4 + tid;
#pragma unroll 4
        for (int j4 = 0; j4 < 32; j4++) {
            float4 w = Wp[j4 * 608];
            unsigned long long w0 = pk2(w.x, w.x), w1 = pk2(w.y, w.y);
            unsigned long long w2 = pk2(w.z, w.z), w3 = pk2(w.w, w.w);
#pragma unroll
            for (int p = 0; p < PAIRS; p++) {
                ulonglong2 xa = xb[p * 64 + j4 * 2];
                ulonglong2 xc = xb[p * 64 + j4 * 2 + 1];
                FMA2(acc[p], w0, xa.x);
                FMA2(acc[p], w1, xa.y);
                FMA2(acc[p], w2, xc.x);
                FMA2(acc[p], w3, xc.y);
            }
        }
#pragma unroll
        for (int p = 0; p < PAIRS; p++) {
            float lo, hi;
            upk2(acc[p], lo, hi);
            gsm[(2 * p) * 608 + tid]     = lo;
            gsm[(2 * p + 1) * 608 + tid] = hi;
        }
    };

    // --- gate phase: GRU nonlinearity, update x / leaky(x), row maxima -------
    auto gatephase = [&](bool step1) -> bool {
        bool changed = false;
        for (int m = tid; m < 14 * HH; m += NT) {
            int r = m >> 7, k = m & 127;
            if (r < nv) {
                float rpre = gsm[r * 608 + k];
                float zpre = gsm[r * 608 + 128 + k];
                float inp  = gsm[r * 608 + 256 + k];
                float hnp  = gsm[r * 608 + 384 + k];
                float rg = 1.0f / (1.0f + expf(-rpre));
                float zg = 1.0f / (1.0f + expf(-zpre));
                float n  = tanhf(inp + rg * hnp);
                int   xi = ((r >> 1) * HH + k) * 2 + (r & 1);
                float xold = xpg[xi];
                float hn = step1 ? (1.0f - zg) * n
                                 : (1.0f - zg) * n + zg * xold;
                changed |= (__float_as_int(hn) != __float_as_int(xold));
                xpg[xi] = hn;
                xpl[xi] = (hn >= 0.f) ? hn : 0.01f * hn;
            }
        }
        if (tid < nv) {
            float mx = -3.4e38f;
#pragma unroll 4
            for (int c = 0; c < CC; c++) mx = fmaxf(mx, gsm[tid * 608 + 512 + c]);
            msm[tid] = mx;
        }
        return changed;
    };

    const float THR = (float)(1.0 - 1e-05);

    // pre-step: hn0 = GRU(ht, 0)
    matvec(g_W1c4);
    __syncthreads();
    gatephase(true);
    __syncthreads();

    float fval[3];
    int   foff[3];
    int   nslots = 0;
    int   sConv = -1;

    for (int s = 0; s < TSTEPS; s++) {
        matvec(g_Wc4);
        __syncthreads();
        bool changed = gatephase(false);
        int cnt = __syncthreads_count(changed ? 1 : 0);

        // output phase: chars_s = row of gsm[.., 512..608)
        nslots = 0;
        for (int m = tid; m < nv * CC; m += NT) {
            int r = m / CC, c = m - r * CC;
            float ch = gsm[r * 608 + 512 + c];
            float cn = __fdiv_rn(ch, msm[r]);
            float val = (cn > THR) ? cn : 0.f;
            int off = (base + r) * (TSTEPS * CC) + c;
            out[(size_t)off + (size_t)s * CC] = val;
            if (c == 52 && val == 1.0f && lensm[r] == 0) lensm[r] = s + 1;
            fval[nslots] = val;
            foff[nslots] = off;
            nslots++;
        }

        if (cnt == 0) { sConv = s; break; }
        __syncthreads();
    }

    if (sConv >= 0) {
        // bitwise fixed point: every future chars row is identical -> replicate
        for (int s2 = sConv + 1; s2 < TSTEPS; s2++) {
#pragma unroll
            for (int q = 0; q < 3; q++) {
                if (q < nslots) out[(size_t)foff[q] + (size_t)s2 * CC] = fval[q];
            }
        }
    }

    __syncthreads();
    if (hasLens && tid < nv) {
        int L = lensm[tid];
        out[(size_t)TITLES_ELEMS + base + tid] = (float)(L == 0 ? TSTEPS : L);
    }
}

// ------------------------------- launch -------------------------------------
extern "C" void kernel_launch(void* const* d_in, const int* in_sizes, int n_in,
                              void* d_out, int out_size) {
    const float* img_feat = (const float*)d_in[0];
    const float* lin1_w   = (const float*)d_in[1];
    const float* lin1_b   = (const float*)d_in[2];
    const float* w_ih     = (const float*)d_in[3];
    const float* w_hh     = (const float*)d_in[4];
    const float* b_ih     = (const float*)d_in[5];
    const float* b_hh     = (const float*)d_in[6];
    const float* lin2_w   = (const float*)d_in[7];
    const float* lin2_b   = (const float*)d_in[8];

    prep_kernel<<<264, 256>>>(lin1_w, w_ih, w_hh, b_ih, b_hh, lin2_w, lin2_b);
    k0_kernel<<<128, 256>>>(img_feat, lin1_b);

    int hasLens = (out_size >= TITLES_ELEMS + BB) ? 1 : 0;
    main_kernel<<<148, 608>>>((float*)d_out, hasLens);
}